// round 11
// baseline (speedup 1.0000x reference)
#include <cuda_runtime.h>
#include <cuda_fp16.h>
#include <math.h>

#define GX 128
#define GY 128
#define GZ 128
#define VDIM 28
#define NUM_RAYS 8192
#define NUM_SAMPLES 128
#define NVOX (GX*GY*GZ)

// Paired reduced grid ([x][y][z] layout): entry v holds fp16 (sigma,r,g,b) for
// voxel v AND voxel v+1 (+z). One aligned uint4 load = both z-corners. 32 MB.
__device__ uint4 g_pairs[NVOX];
__device__ int   g_sink;    // defeats dead-code elimination in prefetch

// ---------------------------------------------------------------------------
// SH basis (degree 2), reference coefficient order.
// ---------------------------------------------------------------------------
__device__ __forceinline__ void sh_basis9(const float* __restrict__ ang, float* b) {
    float theta = ang[0], phi = ang[1];
    float st, ct, sp, cp;
    __sincosf(theta, &st, &ct);
    __sincosf(phi, &sp, &cp);
    const float y00 = 0.28209479177387814f;
    const float h3  = 0.4886025119029199f;
    const float q5  = 0.31539156525252005f;
    const float h15 = 1.0925484305920792f;
    const float q15 = 0.5462742152960396f;
    b[0] = y00;
    b[1] = h3 * st * sp;
    b[2] = h3 * ct;
    b[3] = h3 * st * cp;
    b[4] = h15 * st * cp * st * sp;
    b[5] = h15 * st * sp * ct;
    b[6] = q5 * (3.0f * ct * ct - 1.0f);
    b[7] = h15 * st * cp * ct;
    b[8] = q15 * ((st * cp) * (st * cp) - (st * sp) * (st * sp));
}

// Contract 28 features of voxel v -> packed fp16 (sigma,r | g,b).
__device__ __forceinline__ uint2 contract_voxel(const float* __restrict__ grid,
                                                const float* __restrict__ b, int v) {
    const float4* vp = (const float4*)(grid + (size_t)v * VDIM);
    float f[VDIM];
    #pragma unroll
    for (int i = 0; i < 7; i++) {
        float4 t = __ldcs(vp + i);    // evict-first stream
        f[i*4+0] = t.x; f[i*4+1] = t.y; f[i*4+2] = t.z; f[i*4+3] = t.w;
    }
    float r = 0.f, g = 0.f, bl = 0.f;
    #pragma unroll
    for (int k = 0; k < 9; k++) {
        r  = fmaf(f[1  + k], b[k], r);
        g  = fmaf(f[10 + k], b[k], g);
        bl = fmaf(f[19 + k], b[k], bl);
    }
    __half2 h0 = __floats2half2_rn(f[0], r);
    __half2 h1 = __floats2half2_rn(g, bl);
    uint2 u;
    u.x = *(const unsigned int*)&h0;
    u.y = *(const unsigned int*)&h1;
    return u;
}

// ---------------------------------------------------------------------------
// Kernel 1: contract + pack with +z neighbor (smem supplies the neighbor).
// ---------------------------------------------------------------------------
__global__ __launch_bounds__(256) void reduce_kernel(
    const float* __restrict__ grid, const float* __restrict__ ang)
{
    __shared__ uint2 s[257];
    float b[9];
    sh_basis9(ang, b);

    int base = blockIdx.x * 256;
    int t = threadIdx.x;
    int v = base + t;
    s[t] = contract_voxel(grid, b, v);
    if (t == 0) {
        int v2 = base + 256;
        if (v2 >= NVOX) v2 = NVOX - 1;   // value never read; keep in-bounds
        s[256] = contract_voxel(grid, b, v2);
    }
    __syncthreads();
    uint2 a = s[t], c = s[t + 1];
    g_pairs[v] = make_uint4(a.x, a.y, c.x, c.y);
}

// ---------------------------------------------------------------------------
// Kernel 1.5: sequential L2-repopulation sweep of g_pairs (32 MB, coalesced).
// Converts render's 32 MB of random DRAM misses into a full-BW linear fetch.
// ---------------------------------------------------------------------------
__global__ __launch_bounds__(256) void prefetch_kernel()
{
    int base = blockIdx.x * (256 * 8) + threadIdx.x;
    unsigned acc = 0;
    #pragma unroll
    for (int k = 0; k < 8; k++) {
        uint4 v = __ldcg(&g_pairs[base + k * 256]);   // allocate in L2
        acc ^= v.x ^ v.y ^ v.z ^ v.w;
    }
    if (acc == 0xDEADBEEFu) g_sink = (int)acc;        // never taken in practice
}

// ---------------------------------------------------------------------------
// Kernel 2: rendering, one sample per thread; 4 uint4 gathers (now L2 hits).
// 128 threads (4 warps) per ray, 2 rays per 256-thread block.
// ---------------------------------------------------------------------------
__device__ __forceinline__ float4 zlerp_pair(uint4 t, float zd) {
    float2 a0 = __half22float2(*(__half2*)&t.x);
    float2 a1 = __half22float2(*(__half2*)&t.y);
    float2 b0 = __half22float2(*(__half2*)&t.z);
    float2 b1 = __half22float2(*(__half2*)&t.w);
    return make_float4(fmaf(b0.x - a0.x, zd, a0.x),
                       fmaf(b0.y - a0.y, zd, a0.y),
                       fmaf(b1.x - a1.x, zd, a1.x),
                       fmaf(b1.y - a1.y, zd, a1.y));
}

__device__ __forceinline__ float4 f4lerp(float4 a, float4 b, float t) {
    return make_float4(fmaf(b.x - a.x, t, a.x),
                       fmaf(b.y - a.y, t, a.y),
                       fmaf(b.z - a.z, t, a.z),
                       fmaf(b.w - a.w, t, a.w));
}

__device__ __forceinline__ float4 trilerp(float x, float y, float z) {
    int xi = (int)x, yi = (int)y, zi = (int)z;   // positions in [0, 126]
    float xd = x - (float)xi, yd = y - (float)yi, zd = z - (float)zi;
    int i = (xi << 14) + (yi << 7) + zi;
    const uint4* __restrict__ G = g_pairs;
    uint4 t00 = __ldcg(G + i);                 // (x0,y0)
    uint4 t01 = __ldcg(G + i + GZ);            // (x0,y1)
    uint4 t10 = __ldcg(G + i + GY*GZ);         // (x1,y0)
    uint4 t11 = __ldcg(G + i + GY*GZ + GZ);    // (x1,y1)
    float4 v00 = zlerp_pair(t00, zd);
    float4 v01 = zlerp_pair(t01, zd);
    float4 v10 = zlerp_pair(t10, zd);
    float4 v11 = zlerp_pair(t11, zd);
    float4 v0 = f4lerp(v00, v10, xd);
    float4 v1 = f4lerp(v01, v11, xd);
    return f4lerp(v0, v1, yd);
}

__global__ __launch_bounds__(256) void render_kernel(
    const float* __restrict__ pos, const float* __restrict__ dist,
    float* __restrict__ out)
{
    __shared__ float s_wsum[8];      // per-warp att totals
    __shared__ float s_acc[8][3];    // per-warp rgb partials

    int tid  = threadIdx.x;
    int wid  = tid >> 5;             // warp in block: 0..7
    int lane = tid & 31;
    int wir  = wid & 3;              // warp within ray: 0..3
    int rbase = wid & 4;             // first warp index of this thread's ray
    int ray  = blockIdx.x * 2 + (tid >> 7);
    int s    = tid & 127;            // sample index within ray

    // One-touch streams: evict-first so they don't displace g_pairs.
    const float* p = pos + (size_t)ray * (NUM_SAMPLES * 3) + s * 3;
    float px = __ldcs(p + 0), py = __ldcs(p + 1), pz = __ldcs(p + 2);
    float d  = __ldcs(dist + (size_t)ray * NUM_SAMPLES + s);

    float4 sm = trilerp(px, py, pz);
    float att = __expf(-sm.x * d);

    // Inclusive scan of att over the ray's 128 samples.
    float inc = att;
    #pragma unroll
    for (int o = 1; o < 32; o <<= 1) {
        float n = __shfl_up_sync(0xffffffffu, inc, o);
        if (lane >= o) inc += n;
    }
    if (lane == 31) s_wsum[wid] = inc;
    __syncthreads();
    float off = 0.f;
    #pragma unroll
    for (int w = 0; w < 3; w++)
        if (w < wir) off += s_wsum[rbase + w];
    float T = inc + off;

    float w = T * (1.0f - att);
    float ar = w * sm.y, ag = w * sm.z, ab = w * sm.w;

    #pragma unroll
    for (int o = 16; o > 0; o >>= 1) {
        ar += __shfl_xor_sync(0xffffffffu, ar, o);
        ag += __shfl_xor_sync(0xffffffffu, ag, o);
        ab += __shfl_xor_sync(0xffffffffu, ab, o);
    }
    if (lane == 0) {
        s_acc[wid][0] = ar;
        s_acc[wid][1] = ag;
        s_acc[wid][2] = ab;
    }
    __syncthreads();
    if (wir == 0 && lane < 3) {
        float v = s_acc[rbase + 0][lane] + s_acc[rbase + 1][lane]
                + s_acc[rbase + 2][lane] + s_acc[rbase + 3][lane];
        out[ray * 3 + lane] = v;
    }
}

extern "C" void kernel_launch(void* const* d_in, const int* in_sizes, int n_in,
                              void* d_out, int out_size) {
    const float* voxel_grid = (const float*)d_in[0];
    const float* sample_positions = (const float*)d_in[1];
    const float* sample_distances = (const float*)d_in[2];
    const float* viewing_angle = (const float*)d_in[3];
    float* out = (float*)d_out;

    reduce_kernel<<<NVOX / 256, 256>>>(voxel_grid, viewing_angle);
    prefetch_kernel<<<NVOX / (256 * 8), 256>>>();
    render_kernel<<<NUM_RAYS / 2, 256>>>(sample_positions, sample_distances, out);
}

// round 12
// speedup vs baseline: 1.2517x; 1.2517x over previous
#include <cuda_runtime.h>
#include <cuda_fp16.h>
#include <math.h>

#define GX 128
#define GY 128
#define GZ 128
#define VDIM 28
#define NUM_RAYS 8192
#define NUM_SAMPLES 128
#define NVOX (GX*GY*GZ)

// Paired reduced grid ([x][y][z] layout): entry v holds fp16 (sigma,r,g,b) for
// voxel v AND voxel v+1 (+z). One aligned uint4 load = both z-corners. 32 MB.
__device__ uint4 g_pairs[NVOX];

// ---------------------------------------------------------------------------
// SH basis (degree 2), reference coefficient order.
// ---------------------------------------------------------------------------
__device__ __forceinline__ void sh_basis9(const float* __restrict__ ang, float* b) {
    float theta = ang[0], phi = ang[1];
    float st, ct, sp, cp;
    __sincosf(theta, &st, &ct);
    __sincosf(phi, &sp, &cp);
    const float y00 = 0.28209479177387814f;
    const float h3  = 0.4886025119029199f;
    const float q5  = 0.31539156525252005f;
    const float h15 = 1.0925484305920792f;
    const float q15 = 0.5462742152960396f;
    b[0] = y00;
    b[1] = h3 * st * sp;
    b[2] = h3 * ct;
    b[3] = h3 * st * cp;
    b[4] = h15 * st * cp * st * sp;
    b[5] = h15 * st * sp * ct;
    b[6] = q5 * (3.0f * ct * ct - 1.0f);
    b[7] = h15 * st * cp * ct;
    b[8] = q15 * ((st * cp) * (st * cp) - (st * sp) * (st * sp));
}

// Contract from 7 float4s -> packed fp16 (sigma,r | g,b).
__device__ __forceinline__ uint2 contract7(const float4* vp, const float* b) {
    float f[VDIM];
    #pragma unroll
    for (int i = 0; i < 7; i++) {
        float4 t = vp[i];
        f[i*4+0] = t.x; f[i*4+1] = t.y; f[i*4+2] = t.z; f[i*4+3] = t.w;
    }
    float r = 0.f, g = 0.f, bl = 0.f;
    #pragma unroll
    for (int k = 0; k < 9; k++) {
        r  = fmaf(f[1  + k], b[k], r);
        g  = fmaf(f[10 + k], b[k], g);
        bl = fmaf(f[19 + k], b[k], bl);
    }
    __half2 h0 = __floats2half2_rn(f[0], r);
    __half2 h1 = __floats2half2_rn(g, bl);
    uint2 u;
    u.x = *(const unsigned int*)&h0;
    u.y = *(const unsigned int*)&h1;
    return u;
}

// ---------------------------------------------------------------------------
// Kernel 1: contract + pack with +z neighbor.
// Phase 1: flat coalesced load of the block's 28,672 B of raw features into
// smem (4 wavefronts per warp-instruction instead of 28 for strided reads).
// Phase 2: per-voxel contraction from smem (stride-7-float4 reads are
// conflict-free per 8-lane LDS phase), then pair + store.
// ---------------------------------------------------------------------------
__global__ __launch_bounds__(256) void reduce_kernel(
    const float* __restrict__ grid, const float* __restrict__ ang)
{
    __shared__ float4 sraw[7 * 256];   // 28,672 B raw features of 256 voxels
    __shared__ uint2  sres[257];

    float b[9];
    sh_basis9(ang, b);

    int t = threadIdx.x;
    size_t base4 = (size_t)blockIdx.x * (7 * 256);   // float4 index of block start
    const float4* gp = (const float4*)grid;

    #pragma unroll
    for (int k = 0; k < 7; k++) {
        int g = k * 256 + t;
        sraw[g] = __ldcs(gp + base4 + g);            // contiguous, evict-first
    }

    // Halo voxel (base+256) raw data is outside this block's tile: one thread
    // fetches it straight from global (8 small loads; negligible).
    int vbase = blockIdx.x * 256;
    if (t == 0) {
        int v2 = vbase + 256;
        if (v2 >= NVOX) v2 = NVOX - 1;               // value never read; in-bounds
        sres[256] = contract7((const float4*)(grid + (size_t)v2 * VDIM), b);
    }
    __syncthreads();

    sres[t] = contract7(&sraw[t * 7], b);
    __syncthreads();

    uint2 a = sres[t], c = sres[t + 1];
    g_pairs[vbase + t] = make_uint4(a.x, a.y, c.x, c.y);
}

// ---------------------------------------------------------------------------
// Kernel 2: rendering, one sample per thread; 4 uint4 gathers per sample.
// 128 threads (4 warps) per ray, 2 rays per 256-thread block. (R4 champion.)
// ---------------------------------------------------------------------------
__device__ __forceinline__ float4 zlerp_pair(uint4 t, float zd) {
    float2 a0 = __half22float2(*(__half2*)&t.x);
    float2 a1 = __half22float2(*(__half2*)&t.y);
    float2 b0 = __half22float2(*(__half2*)&t.z);
    float2 b1 = __half22float2(*(__half2*)&t.w);
    return make_float4(fmaf(b0.x - a0.x, zd, a0.x),
                       fmaf(b0.y - a0.y, zd, a0.y),
                       fmaf(b1.x - a1.x, zd, a1.x),
                       fmaf(b1.y - a1.y, zd, a1.y));
}

__device__ __forceinline__ float4 f4lerp(float4 a, float4 b, float t) {
    return make_float4(fmaf(b.x - a.x, t, a.x),
                       fmaf(b.y - a.y, t, a.y),
                       fmaf(b.z - a.z, t, a.z),
                       fmaf(b.w - a.w, t, a.w));
}

__device__ __forceinline__ float4 trilerp(float x, float y, float z) {
    int xi = (int)x, yi = (int)y, zi = (int)z;   // positions in [0, 126]
    float xd = x - (float)xi, yd = y - (float)yi, zd = z - (float)zi;
    int i = (xi << 14) + (yi << 7) + zi;
    const uint4* __restrict__ G = g_pairs;
    uint4 t00 = __ldcg(G + i);                 // (x0,y0)
    uint4 t01 = __ldcg(G + i + GZ);            // (x0,y1)
    uint4 t10 = __ldcg(G + i + GY*GZ);         // (x1,y0)
    uint4 t11 = __ldcg(G + i + GY*GZ + GZ);    // (x1,y1)
    float4 v00 = zlerp_pair(t00, zd);
    float4 v01 = zlerp_pair(t01, zd);
    float4 v10 = zlerp_pair(t10, zd);
    float4 v11 = zlerp_pair(t11, zd);
    float4 v0 = f4lerp(v00, v10, xd);
    float4 v1 = f4lerp(v01, v11, xd);
    return f4lerp(v0, v1, yd);
}

__global__ __launch_bounds__(256) void render_kernel(
    const float* __restrict__ pos, const float* __restrict__ dist,
    float* __restrict__ out)
{
    __shared__ float s_wsum[8];      // per-warp att totals
    __shared__ float s_acc[8][3];    // per-warp rgb partials

    int tid  = threadIdx.x;
    int wid  = tid >> 5;             // warp in block: 0..7
    int lane = tid & 31;
    int wir  = wid & 3;              // warp within ray: 0..3
    int rbase = wid & 4;             // first warp index of this thread's ray
    int ray  = blockIdx.x * 2 + (tid >> 7);
    int s    = tid & 127;            // sample index within ray

    const float* p = pos + (size_t)ray * (NUM_SAMPLES * 3) + s * 3;
    float px = p[0], py = p[1], pz = p[2];
    float d  = dist[(size_t)ray * NUM_SAMPLES + s];

    float4 sm = trilerp(px, py, pz);
    float att = __expf(-sm.x * d);

    // Inclusive scan of att over the ray's 128 samples.
    float inc = att;
    #pragma unroll
    for (int o = 1; o < 32; o <<= 1) {
        float n = __shfl_up_sync(0xffffffffu, inc, o);
        if (lane >= o) inc += n;
    }
    if (lane == 31) s_wsum[wid] = inc;
    __syncthreads();
    float off = 0.f;
    #pragma unroll
    for (int w = 0; w < 3; w++)
        if (w < wir) off += s_wsum[rbase + w];
    float T = inc + off;

    float w = T * (1.0f - att);
    float ar = w * sm.y, ag = w * sm.z, ab = w * sm.w;

    #pragma unroll
    for (int o = 16; o > 0; o >>= 1) {
        ar += __shfl_xor_sync(0xffffffffu, ar, o);
        ag += __shfl_xor_sync(0xffffffffu, ag, o);
        ab += __shfl_xor_sync(0xffffffffu, ab, o);
    }
    if (lane == 0) {
        s_acc[wid][0] = ar;
        s_acc[wid][1] = ag;
        s_acc[wid][2] = ab;
    }
    __syncthreads();
    if (wir == 0 && lane < 3) {
        float v = s_acc[rbase + 0][lane] + s_acc[rbase + 1][lane]
                + s_acc[rbase + 2][lane] + s_acc[rbase + 3][lane];
        out[ray * 3 + lane] = v;
    }
}

extern "C" void kernel_launch(void* const* d_in, const int* in_sizes, int n_in,
                              void* d_out, int out_size) {
    const float* voxel_grid = (const float*)d_in[0];
    const float* sample_positions = (const float*)d_in[1];
    const float* sample_distances = (const float*)d_in[2];
    const float* viewing_angle = (const float*)d_in[3];
    float* out = (float*)d_out;

    reduce_kernel<<<NVOX / 256, 256>>>(voxel_grid, viewing_angle);
    render_kernel<<<NUM_RAYS / 2, 256>>>(sample_positions, sample_distances, out);
}